// round 14
// baseline (speedup 1.0000x reference)
#include <cuda_runtime.h>
#include <cstdint>

// ---------------- constants ----------------
#define MAXN    262144
#define MAXCH   256
#define IDXBITS 21
#define IDXMASK ((1u<<IDXBITS)-1u)
#define RAD2    2.25f
#define MINBETA 0.8f

#define GD       11
#define GHALF    8.25f
#define CINV     0.666f
#define SEGCELLS (GD*GD*GD)      // 1331
#define GCELLS   (2*SEGCELLS)
#define HALFC    1024
#define MAXCG    2048
#define MAXSEG   2

// ---------------- device scratch ----------------
static __device__ uint64_t g_keyA[MAXN];
static __device__ float4   g_cand[MAXN];       // globally sorted: x,y,z, w=(seg<<18|idx)
static __device__ float4   g_cand2[MAXN];      // segment-compacted, order preserved
static __device__ uint32_t g_pk1[MAXN];
static __device__ uint32_t g_pk2[MAXN];
static __device__ int      g_bcnt[256];
static __device__ int      g_bcur[256];
static __device__ int      g_bstart[256];
static __device__ int      g_sp  [MAXCH*2];    // per-chunk segment hist (atomic)
static __device__ int      g_segOff[MAXSEG];
static __device__ int      g_segMM [MAXSEG];
static __device__ int      g_rp1 [MAXCH*256];
static __device__ int      g_rp2 [MAXCH*16];
static __device__ int      g_total[2304];
static __device__ int      g_dense[2304];
static __device__ int      g_done;
static __device__ int      g_done2;
static __device__ float4   g_cp[MAXCG];        // export: x,y,z, w=(c2b<<18)|idx
static __device__ int      g_headG[GCELLS];
static __device__ int      g_nxtG[MAXCG];
static __device__ int      g_segCnt[MAXSEG];
static __device__ int      g_pos[MAXN];
static __device__ int      g_M;
static __device__ int      g_nCtot;

// ---------------- helpers ----------------
__device__ __forceinline__ int blkscan_excl(int v, int tid, int* ws) {
    __syncthreads();
    int lane = tid & 31, w = tid >> 5;
    int inc = v;
    #pragma unroll
    for (int o = 1; o < 32; o <<= 1) {
        int u = __shfl_up_sync(0xffffffffu, inc, o);
        if (lane >= o) inc += u;
    }
    if (lane == 31) ws[w] = inc;
    __syncthreads();
    if (tid < 32) {
        int s = ws[tid];
        #pragma unroll
        for (int o = 1; o < 32; o <<= 1) {
            int u = __shfl_up_sync(0xffffffffu, s, o);
            if (lane >= o) s += u;
        }
        ws[tid] = s;
    }
    __syncthreads();
    return (w ? ws[w - 1] : 0) + inc - v;
}

__device__ __forceinline__ float dist2(float ax, float ay, float az,
                                       float bx, float by, float bz) {
    float dx = ax - bx, dy = ay - by, dz = az - bz;
    return fmaf(dz, dz, fmaf(dy, dy, dx * dx));   // matches XLA fma chain
}

__device__ __forceinline__ int cell1(float v) {
    int c = (int)floorf((v + GHALF) * CINV);
    return c < 0 ? 0 : (c > GD - 1 ? GD - 1 : c);
}

// multisplit: stable rank + global position for (chunk, digit) ordering.
template<int NB>
__device__ __forceinline__ int msplit(const int* __restrict__ hist, int nch, int myc,
                                      int d, bool valid, int tid,
                                      int* base, int* pwh, int* ws) {
    for (int i = tid; i < NB * 32; i += 1024) pwh[i] = 0;
    int tot = 0, part = 0;
    if (tid < NB) {
        for (int c = 0; c < nch; c++) {
            int v = hist[c * NB + tid];
            part += (c < myc) ? v : 0;
            tot += v;
        }
    }
    int start = blkscan_excl(tid < NB ? tot : 0, tid, ws);
    if (tid < NB) base[tid] = start + part;
    int lane = tid & 31, w = tid >> 5;
    unsigned mm = __match_any_sync(0xffffffffu, valid ? d : (0x01000000 | lane));
    int lower = __popc(mm & ((1u << lane) - 1u));
    if (valid && lower == 0) pwh[d * 32 + w] = __popc(mm);
    __syncthreads();
    constexpr int PER = (NB * 32 + 1023) / 1024;
    int loc[PER], s = 0;
    #pragma unroll
    for (int j = 0; j < PER; j++) {
        int idx = tid * PER + j;
        loc[j] = (idx < NB * 32) ? pwh[idx] : 0;
        s += loc[j];
    }
    int ex = blkscan_excl(s, tid, ws);
    int run = ex;
    #pragma unroll
    for (int j = 0; j < PER; j++) {
        int idx = tid * PER + j;
        if (idx < NB * 32) { pwh[idx] = run; run += loc[j]; }
    }
    __syncthreads();
    return valid ? (base[d] + (pwh[d * 32 + w] - pwh[d * 32]) + lower) : -1;
}

// ---------------- kernels ----------------
// 1. psrs init + bucket histogram; last block computes bucket starts + g_M
__global__ __launch_bounds__(1024) void k_candcount(const float* __restrict__ betas, int n,
                                                    float* __restrict__ psrs) {
    __shared__ int lh[256];
    __shared__ int ws[32];
    __shared__ int s_last;
    int tid = threadIdx.x;
    if (tid < 256) lh[tid] = 0;
    __syncthreads();
    int gt = blockIdx.x * 1024 + tid;
    if (gt <= n) psrs[gt] = (float)n;
    if (gt < n) {
        float b = betas[gt];
        if (b >= MINBETA) {
            unsigned m = (~__float_as_uint(b)) & 0x7FFFFFu;
            atomicAdd(&lh[m >> 15], 1);
        }
    }
    __syncthreads();
    if (tid < 256 && lh[tid]) atomicAdd(&g_bcnt[tid], lh[tid]);
    __threadfence();
    if (tid == 0) {
        int prev = atomicAdd(&g_done, 1);
        s_last = (prev == (int)gridDim.x - 1) ? 1 : 0;
        if (s_last) g_done = 0;
    }
    __syncthreads();
    if (s_last) {
        __threadfence();
        int v = (tid < 256) ? g_bcnt[tid] : 0;
        int ex = blkscan_excl(v, tid, ws);
        if (tid < 256) g_bstart[tid] = ex;
        if (tid == 255) g_M = ex + v;
    }
}

// 2. scatter candidate keys into buckets (intra-bucket order arbitrary)
__global__ __launch_bounds__(1024) void k_candscatter(const float* __restrict__ betas, int n) {
    __shared__ int lh[256];
    __shared__ int lbase[256];
    int tid = threadIdx.x;
    if (tid < 256) lh[tid] = 0;
    __syncthreads();
    int gt = blockIdx.x * 1024 + tid;
    bool pred = false; int d = 0, slot = 0; uint64_t key = 0;
    if (gt < n) {
        float b = betas[gt];
        if (b >= MINBETA) {
            pred = true;
            unsigned m = (~__float_as_uint(b)) & 0x7FFFFFu;
            d = (int)(m >> 15);
            key = ((uint64_t)m << IDXBITS) | (unsigned)gt;
            slot = atomicAdd(&lh[d], 1);
        }
    }
    __syncthreads();
    if (tid < 256 && lh[tid]) lbase[tid] = atomicAdd(&g_bcur[tid], lh[tid]);
    __syncthreads();
    if (pred) g_keyA[g_bstart[d] + lbase[d] + slot] = key;
}

// 3. exact in-bucket sort + gather coords + per-chunk segment hist
__global__ __launch_bounds__(1024) void k_bucketsort(const float* __restrict__ cc,
                                                     const int* __restrict__ rs, int ns) {
    __shared__ uint64_t skey[2048];
    __shared__ int sbound[8];
    int b = blockIdx.x;
    int B = g_bcnt[b];
    if (B == 0) return;
    int start = g_bstart[b];
    int tid = threadIdx.x;
    int nsb = ns - 2;
    if (tid < nsb) sbound[tid] = rs[tid + 1];
    if (B <= 2048) {
        for (int e = tid; e < B; e += 1024) skey[e] = g_keyA[start + e];
        __syncthreads();
        for (int e = tid; e < B; e += 1024) {
            uint64_t k = skey[e];
            int r = 0;
            for (int j = 0; j < B; j++) r += (skey[j] < k);
            int idx = (int)(k & IDXMASK);
            int seg = 0;
            for (int j = 0; j < nsb; j++) seg += (idx >= sbound[j]);
            float x = cc[3*idx], y = cc[3*idx+1], z = cc[3*idx+2];
            int pos = start + r;
            g_cand[pos] = make_float4(x, y, z, __int_as_float((seg << 18) | idx));
            atomicAdd(&g_sp[(pos >> 10) * 2 + seg], 1);
        }
    } else {
        __syncthreads();
        for (int e = tid; e < B; e += 1024) {
            uint64_t k = g_keyA[start + e];
            int r = 0;
            for (int j = 0; j < B; j++) r += (g_keyA[start + j] < k);
            int idx = (int)(k & IDXMASK);
            int seg = 0;
            for (int j = 0; j < nsb; j++) seg += (idx >= sbound[j]);
            float x = cc[3*idx], y = cc[3*idx+1], z = cc[3*idx+2];
            int pos = start + r;
            g_cand[pos] = make_float4(x, y, z, __int_as_float((seg << 18) | idx));
            atomicAdd(&g_sp[(pos >> 10) * 2 + seg], 1);
        }
    }
}

// 4. stable partition by segment (order preserved) -> g_cand2 + seg offsets
__global__ __launch_bounds__(1024) void k_partseg() {
    __shared__ int base[2];
    __shared__ int pwh[64];
    __shared__ int ws[32];
    int M = g_M;
    int myc = blockIdx.x;
    if (myc * 1024 >= M) return;
    int nch = (M + 1023) >> 10;
    int tid = threadIdx.x;
    int t = myc * 1024 + tid;
    bool valid = t < M;
    float4 f4 = valid ? g_cand[t] : make_float4(0, 0, 0, 0);
    int d = valid ? (__float_as_int(f4.w) >> 18) : 0;
    int pos = msplit<2>(g_sp, nch, myc, d, valid, tid, base, pwh, ws);
    if (valid) g_cand2[pos] = f4;
    if (myc == 0 && tid == 0) {
        int t0 = 0;
        for (int c = 0; c < nch; c++) t0 += g_sp[c * 2 + 0];
        g_segOff[0] = 0; g_segOff[1] = t0;
        g_segMM[0] = t0; g_segMM[1] = M - t0;
    }
}

// 5. greedy NMS: one block per segment, compacted candidates
__global__ __launch_bounds__(1024) void k_greedy() {
    __shared__ float4   scp[HALFC];
    __shared__ int      nxt[HALFC];
    __shared__ int      head[SEGCELLS];
    __shared__ float    chx[1024], chy[1024], chz[1024];
    __shared__ int      chidx[1024];
    __shared__ unsigned salv[32];
    __shared__ int      snC;
    __shared__ int      s_last;
    int tid = threadIdx.x, lane = tid & 31, w = tid >> 5;
    int myseg = blockIdx.x;
    int nseg = gridDim.x;
    for (int c = tid; c < SEGCELLS; c += 1024) head[c] = -1;
    if (tid == 0) snC = 0;
    __syncthreads();

    int base = g_segOff[myseg];
    int cnt  = g_segMM[myseg];
    int nchunks = (cnt + 1023) >> 10;
    // prefetch chunk 0
    float4 f4n = (tid < cnt) ? g_cand2[base + tid] : make_float4(1e30f, 1e30f, 1e30f, 0.f);
    for (int ch = 0; ch < nchunks; ch++) {
        int t = ch * 1024 + tid;
        bool valid = t < cnt;
        float4 f4 = f4n;
        float x = valid ? f4.x : 1e30f;
        float y = valid ? f4.y : 1e30f;
        float z = valid ? f4.z : 1e30f;
        int oi = __float_as_int(f4.w) & 0x3FFFF;
        chx[tid] = x; chy[tid] = y; chz[tid] = z; chidx[tid] = oi;

        // filter: own cell first (early out), then full 27-cell unrolled walk
        bool hit = false;
        if (valid) {
            int cix = (int)floorf((x + GHALF) * CINV);
            int ciy = (int)floorf((y + GHALF) * CINV);
            int ciz = (int)floorf((z + GHALF) * CINV);
            int ocx = min(GD - 1, max(0, cix));
            int ocy = min(GD - 1, max(0, ciy));
            int ocz = min(GD - 1, max(0, ciz));
            int c = head[(ocz * GD + ocy) * GD + ocx];
            while (c >= 0 && !hit) {
                float4 p = scp[c];
                if (dist2(x, y, z, p.x, p.y, p.z) <= RAD2) hit = true;
                c = nxt[c];
            }
            if (!hit) {
                #pragma unroll
                for (int dz = -1; dz <= 1; dz++) {
                    int zz = min(GD - 1, max(0, ciz + dz));
                    #pragma unroll
                    for (int dy = -1; dy <= 1; dy++) {
                        int yy = min(GD - 1, max(0, ciy + dy));
                        #pragma unroll
                        for (int dx = -1; dx <= 1; dx++) {
                            int xx = min(GD - 1, max(0, cix + dx));
                            c = head[(zz * GD + yy) * GD + xx];
                            while (c >= 0 && !hit) {
                                float4 p = scp[c];
                                if (dist2(x, y, z, p.x, p.y, p.z) <= RAD2) hit = true;
                                c = nxt[c];
                            }
                        }
                    }
                }
            }
        }
        bool pending = valid && !hit;
        unsigned bal = __ballot_sync(0xffffffffu, pending);
        if (lane == 0) salv[w] = bal;
        // prefetch next chunk while warp0 resolves
        {
            int tn = (ch + 1) * 1024 + tid;
            f4n = (tn < cnt) ? g_cand2[base + tn] : make_float4(1e30f, 1e30f, 1e30f, 0.f);
        }
        __syncthreads();

        if (w == 0) {
            unsigned wL = salv[lane];
            int nC = snC;
            while (true) {
                int cand = wL ? (lane * 32 + __ffs(wL) - 1) : 2048;
                #pragma unroll
                for (int o = 16; o; o >>= 1)
                    cand = min(cand, __shfl_xor_sync(0xffffffffu, cand, o));
                if (cand >= 2048) break;
                int j = cand;
                if (lane == (j >> 5)) wL &= ~(1u << (j & 31));
                float sx = chx[j], sy = chy[j], sz = chz[j];
                if (nC < HALFC) {
                    if (lane == 0) {
                        scp[nC] = make_float4(sx, sy, sz, __int_as_float(chidx[j]));
                        int cell = (cell1(sz) * GD + cell1(sy)) * GD + cell1(sx);
                        nxt[nC] = head[cell]; head[cell] = nC;
                    }
                    nC++;
                }
                unsigned rem = wL;
                while (rem) {
                    int b = __ffs(rem) - 1; rem &= rem - 1;
                    int jj = lane * 32 + b;
                    if (dist2(chx[jj], chy[jj], chz[jj], sx, sy, sz) <= RAD2)
                        wL &= ~(1u << b);
                }
            }
            if (lane == 0) snC = nC;
        }
        __syncthreads();
    }

    int nC = snC;
    int off = myseg * HALFC;
    for (int e = tid; e < nC; e += 1024) {
        g_cp[off + e] = scp[e];
        g_nxtG[off + e] = nxt[e] < 0 ? -1 : nxt[e] + off;
    }
    for (int c = tid; c < SEGCELLS; c += 1024)
        g_headG[myseg * SEGCELLS + c] = head[c] < 0 ? -1 : head[c] + off;
    __syncthreads();
    if (tid == 0) {
        g_segCnt[myseg] = nC;
        __threadfence();
        int prev = atomicAdd(&g_done2, 1);
        s_last = (prev == nseg - 1) ? 1 : 0;
        if (s_last) g_done2 = 0;
    }
    __syncthreads();
    if (s_last) {
        __threadfence();
        int ntot = 0;
        for (int s = 0; s < nseg; s++) ntot += g_segCnt[s];
        if (tid == 0) g_nCtot = ntot;
        // compute c2b and pack into g_cp.w: (bin<<18)|idx
        for (int s = 0; s < nseg; s++) {
            int cs = g_segCnt[s];
            for (int e = tid; e < cs; e += 1024) {
                float4 p = g_cp[s * HALFC + e];
                int myidx = __float_as_int(p.w);
                int cnt2 = 1;
                for (int s2 = 0; s2 < nseg; s2++) {
                    int cs2 = g_segCnt[s2];
                    for (int e2 = 0; e2 < cs2; e2++)
                        cnt2 += ((__float_as_int(g_cp[s2 * HALFC + e2].w) & 0x3FFFF) < myidx);
                }
                p.w = __int_as_float((cnt2 << 18) | myidx);
                g_cp[s * HALFC + e] = p;
            }
        }
    }
}

// 6. per-point assignment + pk1 + per-chunk hists + global totals
#define P2_SCP  0
#define P2_NXT  32768
#define P2_HEAD 40960
#define P2_HIST 51616
#define P2_SMEM 59840

__global__ __launch_bounds__(1024) void k_phase2(const float* __restrict__ cc,
                                                 const int* __restrict__ rs, int ns,
                                                 int n, float* __restrict__ asso_out) {
    extern __shared__ char sm[];
    float4* scp  = (float4*)(sm + P2_SCP);
    int*    nxt  = (int*)(sm + P2_NXT);
    int*    head = (int*)(sm + P2_HEAD);
    int*    hist = (int*)(sm + P2_HIST);
    __shared__ int sbound[8];
    __shared__ int segcnt[MAXSEG];
    __shared__ int s_ntot;
    int tid = threadIdx.x;
    int nseg = ns - 1;
    if (tid == 0) s_ntot = g_nCtot;
    if (tid < nseg) segcnt[tid] = g_segCnt[tid];
    int nsb = ns - 2;
    if (tid < nsb) sbound[tid] = rs[tid + 1];
    __syncthreads();
    int nb = s_ntot + 1;
    for (int s = 0; s < nseg; s++) {
        int cs = segcnt[s];
        for (int e = tid; e < cs; e += 1024) {
            int g = s * HALFC + e;
            scp[g] = g_cp[g]; nxt[g] = g_nxtG[g];
        }
    }
    for (int c = tid; c < GCELLS; c += 1024) head[c] = g_headG[c];
    for (int b = tid; b < nb; b += 1024) hist[b] = 0;
    __syncthreads();

    int i = blockIdx.x * 1024 + tid;
    if (i < n) {
        float x = cc[3*i], y = cc[3*i+1], z = cc[3*i+2];
        int seg = 0;
        for (int j = 0; j < nsb; j++) seg += (i >= sbound[j]);
        int cix = (int)floorf((x + GHALF) * CINV);
        int ciy = (int)floorf((y + GHALF) * CINV);
        int ciz = (int)floorf((z + GHALF) * CINV);
        int best = 0x7fffffff;
        #pragma unroll
        for (int dz = -1; dz <= 1; dz++) {
            int zz = min(GD - 1, max(0, ciz + dz));
            #pragma unroll
            for (int dy = -1; dy <= 1; dy++) {
                int yy = min(GD - 1, max(0, ciy + dy));
                #pragma unroll
                for (int dx = -1; dx <= 1; dx++) {
                    int xx = min(GD - 1, max(0, cix + dx));
                    int c = head[(seg * SEGCELLS) + (zz * GD + yy) * GD + xx];
                    while (c >= 0) {
                        float4 p = scp[c];
                        if (c < best && dist2(x, y, z, p.x, p.y, p.z) <= RAD2) best = c;
                        c = nxt[c];
                    }
                }
            }
        }
        int bin, assov;
        if (best == 0x7fffffff) { bin = 0; assov = -1; }
        else {
            int psi = __float_as_int(scp[best].w);
            bin = psi >> 18; assov = psi & 0x3FFFF;
        }
        asso_out[i] = (float)assov;
        g_pk1[i] = ((uint32_t)bin << 18) | (uint32_t)i;
        atomicAdd(&hist[bin], 1);
    }
    __syncthreads();
    for (int b = tid; b < nb; b += 1024) {
        int h = hist[b];
        if (h) atomicAdd(&g_total[b], h);
    }
    for (int d = tid; d < 256; d += 1024) {
        int s = 0;
        for (int b = d; b < nb; b += 256) s += hist[b];
        g_rp1[blockIdx.x * 256 + d] = s;
    }
}

// 7. psrs + dense from totals (single block)
__global__ __launch_bounds__(1024) void k_pfxF(float* __restrict__ psrs) {
    __shared__ int ws[32];
    int nb = g_nCtot + 1;
    int tid = threadIdx.x;
    int carry = 0, carry2 = 0;
    #pragma unroll
    for (int j = 0; j < 3; j++) {
        int b = j * 1024 + tid;
        int v = (b < nb) ? g_total[b] : 0;
        int ex = blkscan_excl(v, tid, ws);
        int startb = carry + ex;
        int tb = ws[31];
        int occ = (b < nb && v > 0) ? 1 : 0;
        int exo = blkscan_excl(occ, tid, ws);
        int dr = carry2 + exo;
        if (b < nb) {
            g_dense[b] = dr;
            if (occ) psrs[dr] = (float)startb;
        }
        carry += tb;
        carry2 += ws[31];
    }
    if (tid == 0) psrs[0] = 0.0f;
}

// 8. point sort pass 1 (bits 18..25), pk1 -> pk2, fused 4-bit hist
__global__ __launch_bounds__(1024) void k_scatP1(int n, int nch) {
    __shared__ int base[256];
    __shared__ int pwh[8192];
    __shared__ int ws[32];
    int myc = blockIdx.x;
    int tid = threadIdx.x;
    int t = myc * 1024 + tid;
    bool valid = t < n;
    uint32_t k = valid ? g_pk1[t] : 0;
    int d = (int)((k >> 18) & 255u);
    int pos = msplit<256>(g_rp1, nch, myc, d, valid, tid, base, pwh, ws);
    if (valid) {
        g_pk2[pos] = k;
        int d2 = (int)((k >> 26) & 15u);
        atomicAdd(&g_rp2[(pos >> 10) * 16 + d2], 1);
    }
}

// 9. point sort pass 2 (bits 26..29) + final outputs
__global__ __launch_bounds__(1024) void k_scatP2(int n, int nch,
                                                 float* __restrict__ sids,
                                                 float* __restrict__ belongs) {
    __shared__ int base[16];
    __shared__ int pwh[512];
    __shared__ int ws[32];
    int myc = blockIdx.x;
    int tid = threadIdx.x;
    int t = myc * 1024 + tid;
    bool valid = t < n;
    uint32_t k = valid ? g_pk2[t] : 0;
    int d = (int)((k >> 26) & 15u);
    int pos = msplit<16>(g_rp2, nch, myc, d, valid, tid, base, pwh, ws);
    if (valid) {
        int i = (int)(k & 0x3FFFFu);
        int bin = (int)(k >> 18);
        sids[pos] = (float)i;
        belongs[pos] = (float)g_dense[bin];
        g_pos[i] = pos;
    }
}

// 10. permute data rows; block 0 re-zeroes atomic scratch for next graph replay
__global__ __launch_bounds__(512) void k_copy(const float* __restrict__ data,
                                              float* __restrict__ sdata, int n, int F) {
    if (blockIdx.x == 0) {
        int tid = threadIdx.x;
        for (int i = tid; i < 256; i += 512) { g_bcnt[i] = 0; g_bcur[i] = 0; }
        for (int i = tid; i < MAXCH * 2; i += 512) g_sp[i] = 0;
        for (int i = tid; i < MAXCH * 16; i += 512) g_rp2[i] = 0;
        for (int i = tid; i < 2304; i += 512) g_total[i] = 0;
    }
    int warp = (blockIdx.x * blockDim.x + threadIdx.x) >> 5;
    int lane = threadIdx.x & 31;
    if (warp >= n) return;
    int pos = g_pos[warp];
    const float4* src = (const float4*)(data + (size_t)warp * F);
    float4* dst = (float4*)(sdata + (size_t)pos * F);
    int nf4 = F >> 2;
    for (int k = lane; k < nf4; k += 32) dst[k] = src[k];
}

// ---------------- host launcher ----------------
extern "C" void kernel_launch(void* const* d_in, const int* in_sizes, int n_in,
                              void* d_out, int out_size) {
    const float* data  = (const float*)d_in[0];
    const float* cc    = (const float*)d_in[1];
    const float* betas = (const float*)d_in[2];
    const int*   rs    = (const int*)d_in[3];
    int N = in_sizes[2];
    int F = in_sizes[0] / N;
    int ns = in_sizes[3];
    int nseg = ns - 1;

    float* out     = (float*)d_out;
    float* sdata   = out;
    float* psrs    = out + (size_t)N * F;
    float* sids    = psrs + (N + 1);
    float* asso    = sids + N;
    float* belongs = asso + N;

    int nch = (N + 1023) / 1024;

    cudaFuncSetAttribute(k_phase2, cudaFuncAttributeMaxDynamicSharedMemorySize, P2_SMEM);

    k_candcount<<<nch, 1024>>>(betas, N, psrs);
    k_candscatter<<<nch, 1024>>>(betas, N);
    k_bucketsort<<<256, 1024>>>(cc, rs, ns);
    k_partseg<<<nch, 1024>>>();
    k_greedy<<<nseg, 1024>>>();
    k_phase2<<<nch, 1024, P2_SMEM>>>(cc, rs, ns, N, asso);
    k_pfxF<<<1, 1024>>>(psrs);
    k_scatP1<<<nch, 1024>>>(N, nch);
    k_scatP2<<<nch, 1024>>>(N, nch, sids, belongs);
    k_copy<<<(N + 15) / 16, 512>>>(data, sdata, N, F);
}

// round 15
// speedup vs baseline: 1.3358x; 1.3358x over previous
#include <cuda_runtime.h>
#include <cstdint>

// ---------------- constants ----------------
#define MAXN    262144
#define MAXCH   256
#define IDXBITS 21
#define IDXMASK ((1u<<IDXBITS)-1u)
#define RAD2    2.25f
#define MINBETA 0.8f

#define GD       11
#define GHALF    8.25f
#define CINV     0.666f
#define SEGCELLS (GD*GD*GD)      // 1331
#define GCELLS   (2*SEGCELLS)
#define HALFC    1024
#define MAXCG    2048
#define MAXSEG   2

// ---------------- device scratch ----------------
static __device__ uint64_t g_keyA[MAXN];
static __device__ float4   g_cand[MAXN];       // globally sorted: x,y,z, w=(seg<<18|idx)
static __device__ float4   g_cand2[MAXN];      // segment-compacted, order preserved
static __device__ uint32_t g_pk1[MAXN];
static __device__ uint32_t g_pk2[MAXN];
static __device__ int      g_bcnt[256];
static __device__ int      g_bcur[256];
static __device__ int      g_bstart[256];
static __device__ int      g_sp  [MAXCH*2];    // per-chunk segment hist (atomic)
static __device__ int      g_segOff[MAXSEG];
static __device__ int      g_segMM [MAXSEG];
static __device__ int      g_rp1 [MAXCH*256];
static __device__ int      g_rp2 [MAXCH*16];
static __device__ int      g_total[2304];
static __device__ int      g_dense[2304];
static __device__ int      g_done;
static __device__ int      g_done2;
static __device__ float4   g_cp[MAXCG];
static __device__ int      g_headG[GCELLS];
static __device__ int      g_nxtG[MAXCG];
static __device__ int      g_c2b[MAXCG];
static __device__ int      g_segCnt[MAXSEG];
static __device__ int      g_pos[MAXN];
static __device__ int      g_M;
static __device__ int      g_nCtot;

// ---------------- helpers ----------------
__device__ __forceinline__ int blkscan_excl(int v, int tid, int* ws) {
    __syncthreads();
    int lane = tid & 31, w = tid >> 5;
    int inc = v;
    #pragma unroll
    for (int o = 1; o < 32; o <<= 1) {
        int u = __shfl_up_sync(0xffffffffu, inc, o);
        if (lane >= o) inc += u;
    }
    if (lane == 31) ws[w] = inc;
    __syncthreads();
    if (tid < 32) {
        int s = ws[tid];
        #pragma unroll
        for (int o = 1; o < 32; o <<= 1) {
            int u = __shfl_up_sync(0xffffffffu, s, o);
            if (lane >= o) s += u;
        }
        ws[tid] = s;
    }
    __syncthreads();
    return (w ? ws[w - 1] : 0) + inc - v;
}

__device__ __forceinline__ float dist2(float ax, float ay, float az,
                                       float bx, float by, float bz) {
    float dx = ax - bx, dy = ay - by, dz = az - bz;
    return fmaf(dz, dz, fmaf(dy, dy, dx * dx));   // matches XLA fma chain
}

__device__ __forceinline__ int cell1(float v) {
    int c = (int)floorf((v + GHALF) * CINV);
    return c < 0 ? 0 : (c > GD - 1 ? GD - 1 : c);
}

// multisplit: stable rank + global position for (chunk, digit) ordering.
template<int NB>
__device__ __forceinline__ int msplit(const int* __restrict__ hist, int nch, int myc,
                                      int d, bool valid, int tid,
                                      int* base, int* pwh, int* ws) {
    for (int i = tid; i < NB * 32; i += 1024) pwh[i] = 0;
    int tot = 0, part = 0;
    if (tid < NB) {
        for (int c = 0; c < nch; c++) {
            int v = hist[c * NB + tid];
            part += (c < myc) ? v : 0;
            tot += v;
        }
    }
    int start = blkscan_excl(tid < NB ? tot : 0, tid, ws);
    if (tid < NB) base[tid] = start + part;
    int lane = tid & 31, w = tid >> 5;
    unsigned mm = __match_any_sync(0xffffffffu, valid ? d : (0x01000000 | lane));
    int lower = __popc(mm & ((1u << lane) - 1u));
    if (valid && lower == 0) pwh[d * 32 + w] = __popc(mm);
    __syncthreads();
    constexpr int PER = (NB * 32 + 1023) / 1024;
    int loc[PER], s = 0;
    #pragma unroll
    for (int j = 0; j < PER; j++) {
        int idx = tid * PER + j;
        loc[j] = (idx < NB * 32) ? pwh[idx] : 0;
        s += loc[j];
    }
    int ex = blkscan_excl(s, tid, ws);
    int run = ex;
    #pragma unroll
    for (int j = 0; j < PER; j++) {
        int idx = tid * PER + j;
        if (idx < NB * 32) { pwh[idx] = run; run += loc[j]; }
    }
    __syncthreads();
    return valid ? (base[d] + (pwh[d * 32 + w] - pwh[d * 32]) + lower) : -1;
}

// ---------------- kernels ----------------
// 1. psrs init + bucket histogram; last block computes bucket starts + g_M
__global__ __launch_bounds__(1024) void k_candcount(const float* __restrict__ betas, int n,
                                                    float* __restrict__ psrs) {
    __shared__ int lh[256];
    __shared__ int ws[32];
    __shared__ int s_last;
    int tid = threadIdx.x;
    if (tid < 256) lh[tid] = 0;
    __syncthreads();
    int gt = blockIdx.x * 1024 + tid;
    if (gt <= n) psrs[gt] = (float)n;
    if (gt < n) {
        float b = betas[gt];
        if (b >= MINBETA) {
            unsigned m = (~__float_as_uint(b)) & 0x7FFFFFu;
            atomicAdd(&lh[m >> 15], 1);
        }
    }
    __syncthreads();
    if (tid < 256 && lh[tid]) atomicAdd(&g_bcnt[tid], lh[tid]);
    __threadfence();
    if (tid == 0) {
        int prev = atomicAdd(&g_done, 1);
        s_last = (prev == (int)gridDim.x - 1) ? 1 : 0;
        if (s_last) g_done = 0;
    }
    __syncthreads();
    if (s_last) {
        __threadfence();
        int v = (tid < 256) ? g_bcnt[tid] : 0;
        int ex = blkscan_excl(v, tid, ws);
        if (tid < 256) g_bstart[tid] = ex;
        if (tid == 255) g_M = ex + v;
    }
}

// 2. scatter candidate keys into buckets (intra-bucket order arbitrary)
__global__ __launch_bounds__(1024) void k_candscatter(const float* __restrict__ betas, int n) {
    __shared__ int lh[256];
    __shared__ int lbase[256];
    int tid = threadIdx.x;
    if (tid < 256) lh[tid] = 0;
    __syncthreads();
    int gt = blockIdx.x * 1024 + tid;
    bool pred = false; int d = 0, slot = 0; uint64_t key = 0;
    if (gt < n) {
        float b = betas[gt];
        if (b >= MINBETA) {
            pred = true;
            unsigned m = (~__float_as_uint(b)) & 0x7FFFFFu;
            d = (int)(m >> 15);
            key = ((uint64_t)m << IDXBITS) | (unsigned)gt;
            slot = atomicAdd(&lh[d], 1);
        }
    }
    __syncthreads();
    if (tid < 256 && lh[tid]) lbase[tid] = atomicAdd(&g_bcur[tid], lh[tid]);
    __syncthreads();
    if (pred) g_keyA[g_bstart[d] + lbase[d] + slot] = key;
}

// 3. exact in-bucket sort + gather coords + per-chunk segment hist
__global__ __launch_bounds__(1024) void k_bucketsort(const float* __restrict__ cc,
                                                     const int* __restrict__ rs, int ns) {
    __shared__ uint64_t skey[2048];
    __shared__ int sbound[8];
    int b = blockIdx.x;
    int B = g_bcnt[b];
    if (B == 0) return;
    int start = g_bstart[b];
    int tid = threadIdx.x;
    int nsb = ns - 2;
    if (tid < nsb) sbound[tid] = rs[tid + 1];
    if (B <= 2048) {
        for (int e = tid; e < B; e += 1024) skey[e] = g_keyA[start + e];
        __syncthreads();
        for (int e = tid; e < B; e += 1024) {
            uint64_t k = skey[e];
            int r = 0;
            for (int j = 0; j < B; j++) r += (skey[j] < k);
            int idx = (int)(k & IDXMASK);
            int seg = 0;
            for (int j = 0; j < nsb; j++) seg += (idx >= sbound[j]);
            float x = cc[3*idx], y = cc[3*idx+1], z = cc[3*idx+2];
            int pos = start + r;
            g_cand[pos] = make_float4(x, y, z, __int_as_float((seg << 18) | idx));
            atomicAdd(&g_sp[(pos >> 10) * 2 + seg], 1);
        }
    } else {
        __syncthreads();
        for (int e = tid; e < B; e += 1024) {
            uint64_t k = g_keyA[start + e];
            int r = 0;
            for (int j = 0; j < B; j++) r += (g_keyA[start + j] < k);
            int idx = (int)(k & IDXMASK);
            int seg = 0;
            for (int j = 0; j < nsb; j++) seg += (idx >= sbound[j]);
            float x = cc[3*idx], y = cc[3*idx+1], z = cc[3*idx+2];
            int pos = start + r;
            g_cand[pos] = make_float4(x, y, z, __int_as_float((seg << 18) | idx));
            atomicAdd(&g_sp[(pos >> 10) * 2 + seg], 1);
        }
    }
}

// 4. stable partition by segment (order preserved) -> g_cand2 + seg offsets
__global__ __launch_bounds__(1024) void k_partseg() {
    __shared__ int base[2];
    __shared__ int pwh[64];
    __shared__ int ws[32];
    int M = g_M;
    int myc = blockIdx.x;
    if (myc * 1024 >= M) return;
    int nch = (M + 1023) >> 10;
    int tid = threadIdx.x;
    int t = myc * 1024 + tid;
    bool valid = t < M;
    float4 f4 = valid ? g_cand[t] : make_float4(0, 0, 0, 0);
    int d = valid ? (__float_as_int(f4.w) >> 18) : 0;
    int pos = msplit<2>(g_sp, nch, myc, d, valid, tid, base, pwh, ws);
    if (valid) g_cand2[pos] = f4;
    if (myc == 0 && tid == 0) {
        int t0 = 0;
        for (int c = 0; c < nch; c++) t0 += g_sp[c * 2 + 0];
        g_segOff[0] = 0; g_segOff[1] = t0;
        g_segMM[0] = t0; g_segMM[1] = M - t0;
    }
}

// 5. greedy NMS: one block per segment, compacted candidates (R13 bodies,
//    micro-chunks of 128 for the first 1024 candidates)
__global__ __launch_bounds__(1024) void k_greedy() {
    __shared__ float4   scp[HALFC];
    __shared__ int      nxt[HALFC];
    __shared__ int      head[SEGCELLS];
    __shared__ float    chx[1024], chy[1024], chz[1024];
    __shared__ int      chidx[1024];
    __shared__ unsigned salv[32];
    __shared__ int      snC;
    __shared__ int      s_last;
    int tid = threadIdx.x, lane = tid & 31, w = tid >> 5;
    int myseg = blockIdx.x;
    int nseg = gridDim.x;
    for (int c = tid; c < SEGCELLS; c += 1024) head[c] = -1;
    if (tid == 0) snC = 0;
    __syncthreads();

    int base = g_segOff[myseg];
    int cnt  = g_segMM[myseg];

    // phase 0: 8 micro-chunks of 128 covering [0,1024); phase 1: 1024-chunks from 1024
    for (int phase = 0; phase < 2; phase++) {
        int csz   = phase ? 1024 : 128;
        int begin = phase ? 1024 : 0;
        int end   = phase ? cnt : (cnt < 1024 ? cnt : 1024);
        for (int off = begin; off < end; off += csz) {
            int t = off + tid;
            bool valid = (tid < csz) && (t < end);
            float x = 1e30f, y = 1e30f, z = 1e30f;
            int oi = 0;
            if (valid) {
                float4 f4 = g_cand2[base + t];
                oi = __float_as_int(f4.w) & 0x3FFFF;
                x = f4.x; y = f4.y; z = f4.z;
            }
            chx[tid] = x; chy[tid] = y; chz[tid] = z; chidx[tid] = oi;

            // filter: fully-unrolled 27-cell walk (R13 body, untouched)
            bool hit = false;
            if (valid) {
                int cix = (int)floorf((x + GHALF) * CINV);
                int ciy = (int)floorf((y + GHALF) * CINV);
                int ciz = (int)floorf((z + GHALF) * CINV);
                #pragma unroll
                for (int dz = -1; dz <= 1; dz++) {
                    int zz = min(GD - 1, max(0, ciz + dz));
                    #pragma unroll
                    for (int dy = -1; dy <= 1; dy++) {
                        int yy = min(GD - 1, max(0, ciy + dy));
                        #pragma unroll
                        for (int dx = -1; dx <= 1; dx++) {
                            int xx = min(GD - 1, max(0, cix + dx));
                            int c = head[(zz * GD + yy) * GD + xx];
                            while (c >= 0 && !hit) {
                                float4 p = scp[c];
                                if (dist2(x, y, z, p.x, p.y, p.z) <= RAD2) hit = true;
                                c = nxt[c];
                            }
                        }
                    }
                }
            }
            bool pending = valid && !hit;
            unsigned bal = __ballot_sync(0xffffffffu, pending);
            if (lane == 0) salv[w] = bal;
            __syncthreads();

            if (w == 0) {
                unsigned wL = salv[lane];
                int nC = snC;
                while (true) {
                    int cand = wL ? (lane * 32 + __ffs(wL) - 1) : 2048;
                    #pragma unroll
                    for (int o = 16; o; o >>= 1)
                        cand = min(cand, __shfl_xor_sync(0xffffffffu, cand, o));
                    if (cand >= 2048) break;
                    int j = cand;
                    if (lane == (j >> 5)) wL &= ~(1u << (j & 31));
                    float sx = chx[j], sy = chy[j], sz = chz[j];
                    if (nC < HALFC) {
                        if (lane == 0) {
                            scp[nC] = make_float4(sx, sy, sz, __int_as_float(chidx[j]));
                            int cell = (cell1(sz) * GD + cell1(sy)) * GD + cell1(sx);
                            nxt[nC] = head[cell]; head[cell] = nC;
                        }
                        nC++;
                    }
                    unsigned rem = wL;
                    while (rem) {
                        int b = __ffs(rem) - 1; rem &= rem - 1;
                        int jj = lane * 32 + b;
                        if (dist2(chx[jj], chy[jj], chz[jj], sx, sy, sz) <= RAD2)
                            wL &= ~(1u << b);
                    }
                }
                if (lane == 0) snC = nC;
            }
            __syncthreads();
        }
    }

    int nC = snC;
    int off2 = myseg * HALFC;
    for (int e = tid; e < nC; e += 1024) {
        g_cp[off2 + e] = scp[e];
        g_nxtG[off2 + e] = nxt[e] < 0 ? -1 : nxt[e] + off2;
    }
    for (int c = tid; c < SEGCELLS; c += 1024)
        g_headG[myseg * SEGCELLS + c] = head[c] < 0 ? -1 : head[c] + off2;
    __syncthreads();
    if (tid == 0) {
        g_segCnt[myseg] = nC;
        __threadfence();
        int prev = atomicAdd(&g_done2, 1);
        s_last = (prev == nseg - 1) ? 1 : 0;
        if (s_last) g_done2 = 0;
    }
    __syncthreads();
    if (s_last) {
        __threadfence();
        int ntot = 0;
        for (int s = 0; s < nseg; s++) ntot += g_segCnt[s];
        if (tid == 0) g_nCtot = ntot;
        for (int s = 0; s < nseg; s++) {
            int cs = g_segCnt[s];
            for (int e = tid; e < cs; e += 1024) {
                int myidx = __float_as_int(g_cp[s * HALFC + e].w);
                int cnt2 = 1;
                for (int s2 = 0; s2 < nseg; s2++) {
                    int cs2 = g_segCnt[s2];
                    for (int e2 = 0; e2 < cs2; e2++)
                        cnt2 += (__float_as_int(g_cp[s2 * HALFC + e2].w) < myidx);
                }
                g_c2b[s * HALFC + e] = cnt2;
            }
        }
    }
}

// 6. per-point assignment + pk1 + per-chunk hists + global totals (R13 filter)
#define P2_SCP  0
#define P2_NXT  32768
#define P2_HEAD 40960
#define P2_C2B  51616
#define P2_HIST 59808
#define P2_SMEM 68032

__global__ __launch_bounds__(1024) void k_phase2(const float* __restrict__ cc,
                                                 const int* __restrict__ rs, int ns,
                                                 int n, float* __restrict__ asso_out) {
    extern __shared__ char sm[];
    float4* scp  = (float4*)(sm + P2_SCP);
    int*    nxt  = (int*)(sm + P2_NXT);
    int*    head = (int*)(sm + P2_HEAD);
    int*    c2b  = (int*)(sm + P2_C2B);
    int*    hist = (int*)(sm + P2_HIST);
    __shared__ int sbound[8];
    __shared__ int segcnt[MAXSEG];
    __shared__ int s_ntot;
    int tid = threadIdx.x;
    int nseg = ns - 1;
    if (tid == 0) s_ntot = g_nCtot;
    if (tid < nseg) segcnt[tid] = g_segCnt[tid];
    int nsb = ns - 2;
    if (tid < nsb) sbound[tid] = rs[tid + 1];
    __syncthreads();
    int nb = s_ntot + 1;
    for (int s = 0; s < nseg; s++) {
        int cs = segcnt[s];
        for (int e = tid; e < cs; e += 1024) {
            int g = s * HALFC + e;
            scp[g] = g_cp[g]; nxt[g] = g_nxtG[g]; c2b[g] = g_c2b[g];
        }
    }
    for (int c = tid; c < GCELLS; c += 1024) head[c] = g_headG[c];
    for (int b = tid; b < nb; b += 1024) hist[b] = 0;
    __syncthreads();

    int i = blockIdx.x * 1024 + tid;
    if (i < n) {
        float x = cc[3*i], y = cc[3*i+1], z = cc[3*i+2];
        int seg = 0;
        for (int j = 0; j < nsb; j++) seg += (i >= sbound[j]);
        int cix = (int)floorf((x + GHALF) * CINV);
        int ciy = (int)floorf((y + GHALF) * CINV);
        int ciz = (int)floorf((z + GHALF) * CINV);
        int best = 0x7fffffff;
        #pragma unroll
        for (int dz = -1; dz <= 1; dz++) {
            int zz = min(GD - 1, max(0, ciz + dz));
            #pragma unroll
            for (int dy = -1; dy <= 1; dy++) {
                int yy = min(GD - 1, max(0, ciy + dy));
                #pragma unroll
                for (int dx = -1; dx <= 1; dx++) {
                    int xx = min(GD - 1, max(0, cix + dx));
                    int c = head[(seg * SEGCELLS) + (zz * GD + yy) * GD + xx];
                    while (c >= 0) {
                        float4 p = scp[c];
                        if (c < best && dist2(x, y, z, p.x, p.y, p.z) <= RAD2) best = c;
                        c = nxt[c];
                    }
                }
            }
        }
        int bin, assov;
        if (best == 0x7fffffff) { bin = 0; assov = -1; }
        else { bin = c2b[best]; assov = __float_as_int(scp[best].w); }
        asso_out[i] = (float)assov;
        g_pk1[i] = ((uint32_t)bin << 18) | (uint32_t)i;
        atomicAdd(&hist[bin], 1);
    }
    __syncthreads();
    for (int b = tid; b < nb; b += 1024) {
        int h = hist[b];
        if (h) atomicAdd(&g_total[b], h);
    }
    for (int d = tid; d < 256; d += 1024) {
        int s = 0;
        for (int b = d; b < nb; b += 256) s += hist[b];
        g_rp1[blockIdx.x * 256 + d] = s;
    }
}

// 7. psrs + dense from totals (single block)
__global__ __launch_bounds__(1024) void k_pfxF(float* __restrict__ psrs) {
    __shared__ int ws[32];
    int nb = g_nCtot + 1;
    int tid = threadIdx.x;
    int carry = 0, carry2 = 0;
    #pragma unroll
    for (int j = 0; j < 3; j++) {
        int b = j * 1024 + tid;
        int v = (b < nb) ? g_total[b] : 0;
        int ex = blkscan_excl(v, tid, ws);
        int startb = carry + ex;
        int tb = ws[31];
        int occ = (b < nb && v > 0) ? 1 : 0;
        int exo = blkscan_excl(occ, tid, ws);
        int dr = carry2 + exo;
        if (b < nb) {
            g_dense[b] = dr;
            if (occ) psrs[dr] = (float)startb;
        }
        carry += tb;
        carry2 += ws[31];
    }
    if (tid == 0) psrs[0] = 0.0f;
}

// 8. point sort pass 1 (bits 18..25), pk1 -> pk2, fused 4-bit hist
__global__ __launch_bounds__(1024) void k_scatP1(int n, int nch) {
    __shared__ int base[256];
    __shared__ int pwh[8192];
    __shared__ int ws[32];
    int myc = blockIdx.x;
    int tid = threadIdx.x;
    int t = myc * 1024 + tid;
    bool valid = t < n;
    uint32_t k = valid ? g_pk1[t] : 0;
    int d = (int)((k >> 18) & 255u);
    int pos = msplit<256>(g_rp1, nch, myc, d, valid, tid, base, pwh, ws);
    if (valid) {
        g_pk2[pos] = k;
        int d2 = (int)((k >> 26) & 15u);
        atomicAdd(&g_rp2[(pos >> 10) * 16 + d2], 1);
    }
}

// 9. point sort pass 2 (bits 26..29) + final outputs
__global__ __launch_bounds__(1024) void k_scatP2(int n, int nch,
                                                 float* __restrict__ sids,
                                                 float* __restrict__ belongs) {
    __shared__ int base[16];
    __shared__ int pwh[512];
    __shared__ int ws[32];
    int myc = blockIdx.x;
    int tid = threadIdx.x;
    int t = myc * 1024 + tid;
    bool valid = t < n;
    uint32_t k = valid ? g_pk2[t] : 0;
    int d = (int)((k >> 26) & 15u);
    int pos = msplit<16>(g_rp2, nch, myc, d, valid, tid, base, pwh, ws);
    if (valid) {
        int i = (int)(k & 0x3FFFFu);
        int bin = (int)(k >> 18);
        sids[pos] = (float)i;
        belongs[pos] = (float)g_dense[bin];
        g_pos[i] = pos;
    }
}

// 10. permute data rows; block 0 re-zeroes atomic scratch for next graph replay
__global__ __launch_bounds__(512) void k_copy(const float* __restrict__ data,
                                              float* __restrict__ sdata, int n, int F) {
    if (blockIdx.x == 0) {
        int tid = threadIdx.x;
        for (int i = tid; i < 256; i += 512) { g_bcnt[i] = 0; g_bcur[i] = 0; }
        for (int i = tid; i < MAXCH * 2; i += 512) g_sp[i] = 0;
        for (int i = tid; i < MAXCH * 16; i += 512) g_rp2[i] = 0;
        for (int i = tid; i < 2304; i += 512) g_total[i] = 0;
    }
    int warp = (blockIdx.x * blockDim.x + threadIdx.x) >> 5;
    int lane = threadIdx.x & 31;
    if (warp >= n) return;
    int pos = g_pos[warp];
    const float4* src = (const float4*)(data + (size_t)warp * F);
    float4* dst = (float4*)(sdata + (size_t)pos * F);
    int nf4 = F >> 2;
    for (int k = lane; k < nf4; k += 32) dst[k] = src[k];
}

// ---------------- host launcher ----------------
extern "C" void kernel_launch(void* const* d_in, const int* in_sizes, int n_in,
                              void* d_out, int out_size) {
    const float* data  = (const float*)d_in[0];
    const float* cc    = (const float*)d_in[1];
    const float* betas = (const float*)d_in[2];
    const int*   rs    = (const int*)d_in[3];
    int N = in_sizes[2];
    int F = in_sizes[0] / N;
    int ns = in_sizes[3];
    int nseg = ns - 1;

    float* out     = (float*)d_out;
    float* sdata   = out;
    float* psrs    = out + (size_t)N * F;
    float* sids    = psrs + (N + 1);
    float* asso    = sids + N;
    float* belongs = asso + N;

    int nch = (N + 1023) / 1024;

    cudaFuncSetAttribute(k_phase2, cudaFuncAttributeMaxDynamicSharedMemorySize, P2_SMEM);

    k_candcount<<<nch, 1024>>>(betas, N, psrs);
    k_candscatter<<<nch, 1024>>>(betas, N);
    k_bucketsort<<<256, 1024>>>(cc, rs, ns);
    k_partseg<<<nch, 1024>>>();
    k_greedy<<<nseg, 1024>>>();
    k_phase2<<<nch, 1024, P2_SMEM>>>(cc, rs, ns, N, asso);
    k_pfxF<<<1, 1024>>>(psrs);
    k_scatP1<<<nch, 1024>>>(N, nch);
    k_scatP2<<<nch, 1024>>>(N, nch, sids, belongs);
    k_copy<<<(N + 15) / 16, 512>>>(data, sdata, N, F);
}

// round 16
// speedup vs baseline: 1.7027x; 1.2747x over previous
#include <cuda_runtime.h>
#include <cstdint>

// ---------------- constants ----------------
#define MAXN    262144
#define MAXCH   256
#define IDXBITS 21
#define IDXMASK ((1u<<IDXBITS)-1u)
#define RAD2    2.25f
#define MINBETA 0.8f

#define GD       11
#define GHALF    8.25f
#define CINV     0.666f
#define SEGCELLS (GD*GD*GD)      // 1331
#define GCELLS   (2*SEGCELLS)
#define HALFC    1024
#define MAXCG    2048
#define MAXSEG   2

// ---------------- device scratch ----------------
static __device__ uint64_t g_keyA[MAXN];
static __device__ float4   g_cand[MAXN];       // globally sorted / survivor out
static __device__ float4   g_cand2[MAXN];      // segment-compacted, order preserved
static __device__ uint32_t g_pk1[MAXN];
static __device__ uint32_t g_pk2[MAXN];
static __device__ int      g_bcnt[256];
static __device__ int      g_bcur[256];
static __device__ int      g_bstart[256];
static __device__ int      g_sp  [MAXCH*2];    // per-chunk segment hist (atomic)
static __device__ int      g_sp2 [MAXCH*2];    // survivor per-chunk segment hist
static __device__ int      g_segOff[MAXSEG];
static __device__ int      g_segMM [MAXSEG];
static __device__ int      g_segOff2[MAXSEG];
static __device__ int      g_segMM2 [MAXSEG];
static __device__ int      g_rp1 [MAXCH*256];
static __device__ int      g_rp2 [MAXCH*16];
static __device__ int      g_total[2304];
static __device__ int      g_dense[2304];
static __device__ int      g_done;
static __device__ int      g_done2;
static __device__ float4   g_cp[MAXCG];
static __device__ int      g_headG[GCELLS];
static __device__ int      g_nxtG[MAXCG];
static __device__ int      g_c2b[MAXCG];
static __device__ int      g_segCnt[MAXSEG];
static __device__ int      g_pos[MAXN];
static __device__ int      g_M;
static __device__ int      g_nCtot;

// ---------------- helpers ----------------
__device__ __forceinline__ int blkscan_excl(int v, int tid, int* ws) {
    __syncthreads();
    int lane = tid & 31, w = tid >> 5;
    int inc = v;
    #pragma unroll
    for (int o = 1; o < 32; o <<= 1) {
        int u = __shfl_up_sync(0xffffffffu, inc, o);
        if (lane >= o) inc += u;
    }
    if (lane == 31) ws[w] = inc;
    __syncthreads();
    if (tid < 32) {
        int s = ws[tid];
        #pragma unroll
        for (int o = 1; o < 32; o <<= 1) {
            int u = __shfl_up_sync(0xffffffffu, s, o);
            if (lane >= o) s += u;
        }
        ws[tid] = s;
    }
    __syncthreads();
    return (w ? ws[w - 1] : 0) + inc - v;
}

__device__ __forceinline__ float dist2(float ax, float ay, float az,
                                       float bx, float by, float bz) {
    float dx = ax - bx, dy = ay - by, dz = az - bz;
    return fmaf(dz, dz, fmaf(dy, dy, dx * dx));   // matches XLA fma chain
}

__device__ __forceinline__ int cell1(float v) {
    int c = (int)floorf((v + GHALF) * CINV);
    return c < 0 ? 0 : (c > GD - 1 ? GD - 1 : c);
}

// multisplit: stable rank + global position for (chunk, digit) ordering.
template<int NB>
__device__ __forceinline__ int msplit(const int* __restrict__ hist, int nch, int myc,
                                      int d, bool valid, int tid,
                                      int* base, int* pwh, int* ws) {
    for (int i = tid; i < NB * 32; i += 1024) pwh[i] = 0;
    int tot = 0, part = 0;
    if (tid < NB) {
        for (int c = 0; c < nch; c++) {
            int v = hist[c * NB + tid];
            part += (c < myc) ? v : 0;
            tot += v;
        }
    }
    int start = blkscan_excl(tid < NB ? tot : 0, tid, ws);
    if (tid < NB) base[tid] = start + part;
    int lane = tid & 31, w = tid >> 5;
    unsigned mm = __match_any_sync(0xffffffffu, valid ? d : (0x01000000 | lane));
    int lower = __popc(mm & ((1u << lane) - 1u));
    if (valid && lower == 0) pwh[d * 32 + w] = __popc(mm);
    __syncthreads();
    constexpr int PER = (NB * 32 + 1023) / 1024;
    int loc[PER], s = 0;
    #pragma unroll
    for (int j = 0; j < PER; j++) {
        int idx = tid * PER + j;
        loc[j] = (idx < NB * 32) ? pwh[idx] : 0;
        s += loc[j];
    }
    int ex = blkscan_excl(s, tid, ws);
    int run = ex;
    #pragma unroll
    for (int j = 0; j < PER; j++) {
        int idx = tid * PER + j;
        if (idx < NB * 32) { pwh[idx] = run; run += loc[j]; }
    }
    __syncthreads();
    return valid ? (base[d] + (pwh[d * 32 + w] - pwh[d * 32]) + lower) : -1;
}

// ---------------- kernels ----------------
// 1. psrs init + bucket histogram; last block computes bucket starts + g_M
__global__ __launch_bounds__(1024) void k_candcount(const float* __restrict__ betas, int n,
                                                    float* __restrict__ psrs) {
    __shared__ int lh[256];
    __shared__ int ws[32];
    __shared__ int s_last;
    int tid = threadIdx.x;
    if (tid < 256) lh[tid] = 0;
    __syncthreads();
    int gt = blockIdx.x * 1024 + tid;
    if (gt <= n) psrs[gt] = (float)n;
    if (gt < n) {
        float b = betas[gt];
        if (b >= MINBETA) {
            unsigned m = (~__float_as_uint(b)) & 0x7FFFFFu;
            atomicAdd(&lh[m >> 15], 1);
        }
    }
    __syncthreads();
    if (tid < 256 && lh[tid]) atomicAdd(&g_bcnt[tid], lh[tid]);
    __threadfence();
    if (tid == 0) {
        int prev = atomicAdd(&g_done, 1);
        s_last = (prev == (int)gridDim.x - 1) ? 1 : 0;
        if (s_last) g_done = 0;
    }
    __syncthreads();
    if (s_last) {
        __threadfence();
        int v = (tid < 256) ? g_bcnt[tid] : 0;
        int ex = blkscan_excl(v, tid, ws);
        if (tid < 256) g_bstart[tid] = ex;
        if (tid == 255) g_M = ex + v;
    }
}

// 2. scatter candidate keys into buckets (intra-bucket order arbitrary)
__global__ __launch_bounds__(1024) void k_candscatter(const float* __restrict__ betas, int n) {
    __shared__ int lh[256];
    __shared__ int lbase[256];
    int tid = threadIdx.x;
    if (tid < 256) lh[tid] = 0;
    __syncthreads();
    int gt = blockIdx.x * 1024 + tid;
    bool pred = false; int d = 0, slot = 0; uint64_t key = 0;
    if (gt < n) {
        float b = betas[gt];
        if (b >= MINBETA) {
            pred = true;
            unsigned m = (~__float_as_uint(b)) & 0x7FFFFFu;
            d = (int)(m >> 15);
            key = ((uint64_t)m << IDXBITS) | (unsigned)gt;
            slot = atomicAdd(&lh[d], 1);
        }
    }
    __syncthreads();
    if (tid < 256 && lh[tid]) lbase[tid] = atomicAdd(&g_bcur[tid], lh[tid]);
    __syncthreads();
    if (pred) g_keyA[g_bstart[d] + lbase[d] + slot] = key;
}

// 3. exact in-bucket sort + gather coords + per-chunk segment hist
__global__ __launch_bounds__(1024) void k_bucketsort(const float* __restrict__ cc,
                                                     const int* __restrict__ rs, int ns) {
    __shared__ uint64_t skey[2048];
    __shared__ int sbound[8];
    int b = blockIdx.x;
    int B = g_bcnt[b];
    if (B == 0) return;
    int start = g_bstart[b];
    int tid = threadIdx.x;
    int nsb = ns - 2;
    if (tid < nsb) sbound[tid] = rs[tid + 1];
    if (B <= 2048) {
        for (int e = tid; e < B; e += 1024) skey[e] = g_keyA[start + e];
        __syncthreads();
        for (int e = tid; e < B; e += 1024) {
            uint64_t k = skey[e];
            int r = 0;
            for (int j = 0; j < B; j++) r += (skey[j] < k);
            int idx = (int)(k & IDXMASK);
            int seg = 0;
            for (int j = 0; j < nsb; j++) seg += (idx >= sbound[j]);
            float x = cc[3*idx], y = cc[3*idx+1], z = cc[3*idx+2];
            int pos = start + r;
            g_cand[pos] = make_float4(x, y, z, __int_as_float((seg << 18) | idx));
            atomicAdd(&g_sp[(pos >> 10) * 2 + seg], 1);
        }
    } else {
        __syncthreads();
        for (int e = tid; e < B; e += 1024) {
            uint64_t k = g_keyA[start + e];
            int r = 0;
            for (int j = 0; j < B; j++) r += (g_keyA[start + j] < k);
            int idx = (int)(k & IDXMASK);
            int seg = 0;
            for (int j = 0; j < nsb; j++) seg += (idx >= sbound[j]);
            float x = cc[3*idx], y = cc[3*idx+1], z = cc[3*idx+2];
            int pos = start + r;
            g_cand[pos] = make_float4(x, y, z, __int_as_float((seg << 18) | idx));
            atomicAdd(&g_sp[(pos >> 10) * 2 + seg], 1);
        }
    }
}

// 4. stable partition by segment (order preserved) -> g_cand2 + seg offsets
__global__ __launch_bounds__(1024) void k_partseg() {
    __shared__ int base[2];
    __shared__ int pwh[64];
    __shared__ int ws[32];
    int M = g_M;
    int myc = blockIdx.x;
    if (myc * 1024 >= M) return;
    int nch = (M + 1023) >> 10;
    int tid = threadIdx.x;
    int t = myc * 1024 + tid;
    bool valid = t < M;
    float4 f4 = valid ? g_cand[t] : make_float4(0, 0, 0, 0);
    int d = valid ? (__float_as_int(f4.w) >> 18) : 0;
    int pos = msplit<2>(g_sp, nch, myc, d, valid, tid, base, pwh, ws);
    if (valid) g_cand2[pos] = f4;
    if (myc == 0 && tid == 0) {
        int t0 = 0;
        for (int c = 0; c < nch; c++) t0 += g_sp[c * 2 + 0];
        g_segOff[0] = 0; g_segOff[1] = t0;
        g_segMM[0] = t0; g_segMM[1] = M - t0;
    }
}

// 5. greedy A: R13 greedy over ONLY the first 1024 candidates per segment.
__global__ __launch_bounds__(1024) void k_greedyA() {
    __shared__ float4   scp[HALFC];
    __shared__ int      nxt[HALFC];
    __shared__ int      head[SEGCELLS];
    __shared__ float    chx[1024], chy[1024], chz[1024];
    __shared__ int      chidx[1024];
    __shared__ unsigned salv[32];
    __shared__ int      snC;
    int tid = threadIdx.x, lane = tid & 31, w = tid >> 5;
    int myseg = blockIdx.x;
    for (int c = tid; c < SEGCELLS; c += 1024) head[c] = -1;
    if (tid == 0) snC = 0;
    __syncthreads();

    int base = g_segOff[myseg];
    int cnt  = g_segMM[myseg];
    int end  = cnt < 1024 ? cnt : 1024;
    {
        int t = tid;
        bool valid = t < end;
        float x = 1e30f, y = 1e30f, z = 1e30f;
        int oi = 0;
        if (valid) {
            float4 f4 = g_cand2[base + t];
            oi = __float_as_int(f4.w) & 0x3FFFF;
            x = f4.x; y = f4.y; z = f4.z;
        }
        chx[tid] = x; chy[tid] = y; chz[tid] = z; chidx[tid] = oi;

        bool pending = valid;         // no cpoints yet: all valid are pending
        unsigned bal = __ballot_sync(0xffffffffu, pending);
        if (lane == 0) salv[w] = bal;
        __syncthreads();

        if (w == 0) {
            unsigned wL = salv[lane];
            int nC = snC;
            while (true) {
                int cand = wL ? (lane * 32 + __ffs(wL) - 1) : 2048;
                #pragma unroll
                for (int o = 16; o; o >>= 1)
                    cand = min(cand, __shfl_xor_sync(0xffffffffu, cand, o));
                if (cand >= 2048) break;
                int j = cand;
                if (lane == (j >> 5)) wL &= ~(1u << (j & 31));
                float sx = chx[j], sy = chy[j], sz = chz[j];
                if (nC < HALFC) {
                    if (lane == 0) {
                        scp[nC] = make_float4(sx, sy, sz, __int_as_float(chidx[j]));
                        int cell = (cell1(sz) * GD + cell1(sy)) * GD + cell1(sx);
                        nxt[nC] = head[cell]; head[cell] = nC;
                    }
                    nC++;
                }
                unsigned rem = wL;
                while (rem) {
                    int b = __ffs(rem) - 1; rem &= rem - 1;
                    int jj = lane * 32 + b;
                    if (dist2(chx[jj], chy[jj], chz[jj], sx, sy, sz) <= RAD2)
                        wL &= ~(1u << b);
                }
            }
            if (lane == 0) snC = nC;
        }
        __syncthreads();
    }

    int nC = snC;
    int off2 = myseg * HALFC;
    for (int e = tid; e < nC; e += 1024) {
        g_cp[off2 + e] = scp[e];
        g_nxtG[off2 + e] = nxt[e] < 0 ? -1 : nxt[e] + off2;
    }
    for (int c = tid; c < SEGCELLS; c += 1024)
        g_headG[myseg * SEGCELLS + c] = head[c] < 0 ? -1 : head[c] + off2;
    if (tid == 0) g_segCnt[myseg] = nC;
}

// 6. grid-wide refilter of remaining candidates vs S1 (parallel across SMs)
__global__ __launch_bounds__(1024) void k_refilter() {
    int M = g_M;
    if ((int)blockIdx.x * 1024 >= M) return;
    int tid = threadIdx.x;
    int t = blockIdx.x * 1024 + tid;
    bool keep = false; int seg = 0;
    if (t < M) {
        float4 f4 = g_cand2[t];
        int si = __float_as_int(f4.w);
        seg = si >> 18;
        int rel = t - g_segOff[seg];
        if (rel >= 1024) {
            float x = f4.x, y = f4.y, z = f4.z;
            int cix = (int)floorf((x + GHALF) * CINV);
            int ciy = (int)floorf((y + GHALF) * CINV);
            int ciz = (int)floorf((z + GHALF) * CINV);
            bool hit = false;
            #pragma unroll
            for (int dz = -1; dz <= 1; dz++) {
                int zz = min(GD - 1, max(0, ciz + dz));
                #pragma unroll
                for (int dy = -1; dy <= 1; dy++) {
                    int yy = min(GD - 1, max(0, ciy + dy));
                    #pragma unroll
                    for (int dx = -1; dx <= 1; dx++) {
                        int xx = min(GD - 1, max(0, cix + dx));
                        int c = g_headG[seg * SEGCELLS + (zz * GD + yy) * GD + xx];
                        while (c >= 0 && !hit) {
                            float4 p = g_cp[c];
                            if (dist2(x, y, z, p.x, p.y, p.z) <= RAD2) hit = true;
                            c = g_nxtG[c];
                        }
                    }
                }
            }
            keep = !hit;
        }
    }
    g_pk1[t] = keep ? (1u | ((unsigned)seg << 1)) : 0u;
    if (keep) atomicAdd(&g_sp2[(t >> 10) * 2 + seg], 1);
}

// 7. stable compaction of survivors (by segment) -> g_cand + seg offsets 2
__global__ __launch_bounds__(1024) void k_recompact() {
    __shared__ int base[2];
    __shared__ int pwh[64];
    __shared__ int ws[32];
    int M = g_M;
    int myc = blockIdx.x;
    if (myc * 1024 >= M) return;
    int nch = (M + 1023) >> 10;
    int tid = threadIdx.x;
    int t = myc * 1024 + tid;
    bool inrange = t < M;
    unsigned fl = inrange ? g_pk1[t] : 0u;
    bool keep = (fl & 1u) != 0u;
    int d = (int)(fl >> 1);
    int pos = msplit<2>(g_sp2, nch, myc, d, keep, tid, base, pwh, ws);
    if (keep) g_cand[pos] = g_cand2[t];
    if (myc == 0 && tid == 0) {
        int t0 = 0, t1 = 0;
        for (int c = 0; c < nch; c++) { t0 += g_sp2[c * 2 + 0]; t1 += g_sp2[c * 2 + 1]; }
        g_segOff2[0] = 0; g_segOff2[1] = t0;
        g_segMM2[0] = t0; g_segMM2[1] = t1;
    }
}

// 8. greedy B: import S1 state, process survivors (R13 bodies), tail + c2b
__global__ __launch_bounds__(1024) void k_greedyB() {
    __shared__ float4   scp[HALFC];
    __shared__ int      nxt[HALFC];
    __shared__ int      head[SEGCELLS];
    __shared__ float    chx[1024], chy[1024], chz[1024];
    __shared__ int      chidx[1024];
    __shared__ unsigned salv[32];
    __shared__ int      snC;
    __shared__ int      s_last;
    int tid = threadIdx.x, lane = tid & 31, w = tid >> 5;
    int myseg = blockIdx.x;
    int nseg = gridDim.x;
    int off2 = myseg * HALFC;
    // import state from A
    int nC0 = g_segCnt[myseg];
    for (int c = tid; c < SEGCELLS; c += 1024) {
        int h = g_headG[myseg * SEGCELLS + c];
        head[c] = h < 0 ? -1 : h - off2;
    }
    for (int e = tid; e < nC0; e += 1024) {
        scp[e] = g_cp[off2 + e];
        int nx = g_nxtG[off2 + e];
        nxt[e] = nx < 0 ? -1 : nx - off2;
    }
    if (tid == 0) snC = nC0;
    __syncthreads();

    int base = g_segOff2[myseg];
    int cnt  = g_segMM2[myseg];
    for (int off = 0; off < cnt; off += 1024) {
        int t = off + tid;
        bool valid = t < cnt;
        float x = 1e30f, y = 1e30f, z = 1e30f;
        int oi = 0;
        if (valid) {
            float4 f4 = g_cand[base + t];
            oi = __float_as_int(f4.w) & 0x3FFFF;
            x = f4.x; y = f4.y; z = f4.z;
        }
        chx[tid] = x; chy[tid] = y; chz[tid] = z; chidx[tid] = oi;

        // filter vs cpoints added since refilter (grid holds all; correct superset)
        bool hit = false;
        if (valid) {
            int cix = (int)floorf((x + GHALF) * CINV);
            int ciy = (int)floorf((y + GHALF) * CINV);
            int ciz = (int)floorf((z + GHALF) * CINV);
            #pragma unroll
            for (int dz = -1; dz <= 1; dz++) {
                int zz = min(GD - 1, max(0, ciz + dz));
                #pragma unroll
                for (int dy = -1; dy <= 1; dy++) {
                    int yy = min(GD - 1, max(0, ciy + dy));
                    #pragma unroll
                    for (int dx = -1; dx <= 1; dx++) {
                        int xx = min(GD - 1, max(0, cix + dx));
                        int c = head[(zz * GD + yy) * GD + xx];
                        while (c >= 0 && !hit) {
                            float4 p = scp[c];
                            if (dist2(x, y, z, p.x, p.y, p.z) <= RAD2) hit = true;
                            c = nxt[c];
                        }
                    }
                }
            }
        }
        bool pending = valid && !hit;
        unsigned bal = __ballot_sync(0xffffffffu, pending);
        if (lane == 0) salv[w] = bal;
        __syncthreads();

        if (w == 0) {
            unsigned wL = salv[lane];
            int nC = snC;
            while (true) {
                int cand = wL ? (lane * 32 + __ffs(wL) - 1) : 2048;
                #pragma unroll
                for (int o = 16; o; o >>= 1)
                    cand = min(cand, __shfl_xor_sync(0xffffffffu, cand, o));
                if (cand >= 2048) break;
                int j = cand;
                if (lane == (j >> 5)) wL &= ~(1u << (j & 31));
                float sx = chx[j], sy = chy[j], sz = chz[j];
                if (nC < HALFC) {
                    if (lane == 0) {
                        scp[nC] = make_float4(sx, sy, sz, __int_as_float(chidx[j]));
                        int cell = (cell1(sz) * GD + cell1(sy)) * GD + cell1(sx);
                        nxt[nC] = head[cell]; head[cell] = nC;
                    }
                    nC++;
                }
                unsigned rem = wL;
                while (rem) {
                    int b = __ffs(rem) - 1; rem &= rem - 1;
                    int jj = lane * 32 + b;
                    if (dist2(chx[jj], chy[jj], chz[jj], sx, sy, sz) <= RAD2)
                        wL &= ~(1u << b);
                }
            }
            if (lane == 0) snC = nC;
        }
        __syncthreads();
    }

    int nC = snC;
    for (int e = tid; e < nC; e += 1024) {
        g_cp[off2 + e] = scp[e];
        g_nxtG[off2 + e] = nxt[e] < 0 ? -1 : nxt[e] + off2;
    }
    for (int c = tid; c < SEGCELLS; c += 1024)
        g_headG[myseg * SEGCELLS + c] = head[c] < 0 ? -1 : head[c] + off2;
    __syncthreads();
    if (tid == 0) {
        g_segCnt[myseg] = nC;
        __threadfence();
        int prev = atomicAdd(&g_done2, 1);
        s_last = (prev == nseg - 1) ? 1 : 0;
        if (s_last) g_done2 = 0;
    }
    __syncthreads();
    if (s_last) {
        __threadfence();
        int ntot = 0;
        for (int s = 0; s < nseg; s++) ntot += g_segCnt[s];
        if (tid == 0) g_nCtot = ntot;
        for (int s = 0; s < nseg; s++) {
            int cs = g_segCnt[s];
            for (int e = tid; e < cs; e += 1024) {
                int myidx = __float_as_int(g_cp[s * HALFC + e].w);
                int cnt2 = 1;
                for (int s2 = 0; s2 < nseg; s2++) {
                    int cs2 = g_segCnt[s2];
                    for (int e2 = 0; e2 < cs2; e2++)
                        cnt2 += (__float_as_int(g_cp[s2 * HALFC + e2].w) < myidx);
                }
                g_c2b[s * HALFC + e] = cnt2;
            }
        }
    }
}

// 9. per-point assignment + pk1 + per-chunk hists + global totals (R13 filter)
#define P2_SCP  0
#define P2_NXT  32768
#define P2_HEAD 40960
#define P2_C2B  51616
#define P2_HIST 59808
#define P2_SMEM 68032

__global__ __launch_bounds__(1024) void k_phase2(const float* __restrict__ cc,
                                                 const int* __restrict__ rs, int ns,
                                                 int n, float* __restrict__ asso_out) {
    extern __shared__ char sm[];
    float4* scp  = (float4*)(sm + P2_SCP);
    int*    nxt  = (int*)(sm + P2_NXT);
    int*    head = (int*)(sm + P2_HEAD);
    int*    c2b  = (int*)(sm + P2_C2B);
    int*    hist = (int*)(sm + P2_HIST);
    __shared__ int sbound[8];
    __shared__ int segcnt[MAXSEG];
    __shared__ int s_ntot;
    int tid = threadIdx.x;
    int nseg = ns - 1;
    if (tid == 0) s_ntot = g_nCtot;
    if (tid < nseg) segcnt[tid] = g_segCnt[tid];
    int nsb = ns - 2;
    if (tid < nsb) sbound[tid] = rs[tid + 1];
    __syncthreads();
    int nb = s_ntot + 1;
    for (int s = 0; s < nseg; s++) {
        int cs = segcnt[s];
        for (int e = tid; e < cs; e += 1024) {
            int g = s * HALFC + e;
            scp[g] = g_cp[g]; nxt[g] = g_nxtG[g]; c2b[g] = g_c2b[g];
        }
    }
    for (int c = tid; c < GCELLS; c += 1024) head[c] = g_headG[c];
    for (int b = tid; b < nb; b += 1024) hist[b] = 0;
    __syncthreads();

    int i = blockIdx.x * 1024 + tid;
    if (i < n) {
        float x = cc[3*i], y = cc[3*i+1], z = cc[3*i+2];
        int seg = 0;
        for (int j = 0; j < nsb; j++) seg += (i >= sbound[j]);
        int cix = (int)floorf((x + GHALF) * CINV);
        int ciy = (int)floorf((y + GHALF) * CINV);
        int ciz = (int)floorf((z + GHALF) * CINV);
        int best = 0x7fffffff;
        #pragma unroll
        for (int dz = -1; dz <= 1; dz++) {
            int zz = min(GD - 1, max(0, ciz + dz));
            #pragma unroll
            for (int dy = -1; dy <= 1; dy++) {
                int yy = min(GD - 1, max(0, ciy + dy));
                #pragma unroll
                for (int dx = -1; dx <= 1; dx++) {
                    int xx = min(GD - 1, max(0, cix + dx));
                    int c = head[(seg * SEGCELLS) + (zz * GD + yy) * GD + xx];
                    while (c >= 0) {
                        float4 p = scp[c];
                        if (c < best && dist2(x, y, z, p.x, p.y, p.z) <= RAD2) best = c;
                        c = nxt[c];
                    }
                }
            }
        }
        int bin, assov;
        if (best == 0x7fffffff) { bin = 0; assov = -1; }
        else { bin = c2b[best]; assov = __float_as_int(scp[best].w); }
        asso_out[i] = (float)assov;
        g_pk1[i] = ((uint32_t)bin << 18) | (uint32_t)i;
        atomicAdd(&hist[bin], 1);
    }
    __syncthreads();
    for (int b = tid; b < nb; b += 1024) {
        int h = hist[b];
        if (h) atomicAdd(&g_total[b], h);
    }
    for (int d = tid; d < 256; d += 1024) {
        int s = 0;
        for (int b = d; b < nb; b += 256) s += hist[b];
        g_rp1[blockIdx.x * 256 + d] = s;
    }
}

// 10. psrs + dense from totals (single block)
__global__ __launch_bounds__(1024) void k_pfxF(float* __restrict__ psrs) {
    __shared__ int ws[32];
    int nb = g_nCtot + 1;
    int tid = threadIdx.x;
    int carry = 0, carry2 = 0;
    #pragma unroll
    for (int j = 0; j < 3; j++) {
        int b = j * 1024 + tid;
        int v = (b < nb) ? g_total[b] : 0;
        int ex = blkscan_excl(v, tid, ws);
        int startb = carry + ex;
        int tb = ws[31];
        int occ = (b < nb && v > 0) ? 1 : 0;
        int exo = blkscan_excl(occ, tid, ws);
        int dr = carry2 + exo;
        if (b < nb) {
            g_dense[b] = dr;
            if (occ) psrs[dr] = (float)startb;
        }
        carry += tb;
        carry2 += ws[31];
    }
    if (tid == 0) psrs[0] = 0.0f;
}

// 11. point sort pass 1 (bits 18..25), pk1 -> pk2, fused 4-bit hist
__global__ __launch_bounds__(1024) void k_scatP1(int n, int nch) {
    __shared__ int base[256];
    __shared__ int pwh[8192];
    __shared__ int ws[32];
    int myc = blockIdx.x;
    int tid = threadIdx.x;
    int t = myc * 1024 + tid;
    bool valid = t < n;
    uint32_t k = valid ? g_pk1[t] : 0;
    int d = (int)((k >> 18) & 255u);
    int pos = msplit<256>(g_rp1, nch, myc, d, valid, tid, base, pwh, ws);
    if (valid) {
        g_pk2[pos] = k;
        int d2 = (int)((k >> 26) & 15u);
        atomicAdd(&g_rp2[(pos >> 10) * 16 + d2], 1);
    }
}

// 12. point sort pass 2 (bits 26..29) + final outputs
__global__ __launch_bounds__(1024) void k_scatP2(int n, int nch,
                                                 float* __restrict__ sids,
                                                 float* __restrict__ belongs) {
    __shared__ int base[16];
    __shared__ int pwh[512];
    __shared__ int ws[32];
    int myc = blockIdx.x;
    int tid = threadIdx.x;
    int t = myc * 1024 + tid;
    bool valid = t < n;
    uint32_t k = valid ? g_pk2[t] : 0;
    int d = (int)((k >> 26) & 15u);
    int pos = msplit<16>(g_rp2, nch, myc, d, valid, tid, base, pwh, ws);
    if (valid) {
        int i = (int)(k & 0x3FFFFu);
        int bin = (int)(k >> 18);
        sids[pos] = (float)i;
        belongs[pos] = (float)g_dense[bin];
        g_pos[i] = pos;
    }
}

// 13. permute data rows; block 0 re-zeroes atomic scratch for next graph replay
__global__ __launch_bounds__(512) void k_copy(const float* __restrict__ data,
                                              float* __restrict__ sdata, int n, int F) {
    if (blockIdx.x == 0) {
        int tid = threadIdx.x;
        for (int i = tid; i < 256; i += 512) { g_bcnt[i] = 0; g_bcur[i] = 0; }
        for (int i = tid; i < MAXCH * 2; i += 512) { g_sp[i] = 0; g_sp2[i] = 0; }
        for (int i = tid; i < MAXCH * 16; i += 512) g_rp2[i] = 0;
        for (int i = tid; i < 2304; i += 512) g_total[i] = 0;
    }
    int warp = (blockIdx.x * blockDim.x + threadIdx.x) >> 5;
    int lane = threadIdx.x & 31;
    if (warp >= n) return;
    int pos = g_pos[warp];
    const float4* src = (const float4*)(data + (size_t)warp * F);
    float4* dst = (float4*)(sdata + (size_t)pos * F);
    int nf4 = F >> 2;
    for (int k = lane; k < nf4; k += 32) dst[k] = src[k];
}

// ---------------- host launcher ----------------
extern "C" void kernel_launch(void* const* d_in, const int* in_sizes, int n_in,
                              void* d_out, int out_size) {
    const float* data  = (const float*)d_in[0];
    const float* cc    = (const float*)d_in[1];
    const float* betas = (const float*)d_in[2];
    const int*   rs    = (const int*)d_in[3];
    int N = in_sizes[2];
    int F = in_sizes[0] / N;
    int ns = in_sizes[3];
    int nseg = ns - 1;

    float* out     = (float*)d_out;
    float* sdata   = out;
    float* psrs    = out + (size_t)N * F;
    float* sids    = psrs + (N + 1);
    float* asso    = sids + N;
    float* belongs = asso + N;

    int nch = (N + 1023) / 1024;

    cudaFuncSetAttribute(k_phase2, cudaFuncAttributeMaxDynamicSharedMemorySize, P2_SMEM);

    k_candcount<<<nch, 1024>>>(betas, N, psrs);
    k_candscatter<<<nch, 1024>>>(betas, N);
    k_bucketsort<<<256, 1024>>>(cc, rs, ns);
    k_partseg<<<nch, 1024>>>();
    k_greedyA<<<nseg, 1024>>>();
    k_refilter<<<nch, 1024>>>();
    k_recompact<<<nch, 1024>>>();
    k_greedyB<<<nseg, 1024>>>();
    k_phase2<<<nch, 1024, P2_SMEM>>>(cc, rs, ns, N, asso);
    k_pfxF<<<1, 1024>>>(psrs);
    k_scatP1<<<nch, 1024>>>(N, nch);
    k_scatP2<<<nch, 1024>>>(N, nch, sids, belongs);
    k_copy<<<(N + 15) / 16, 512>>>(data, sdata, N, F);
}